// round 1
// baseline (speedup 1.0000x reference)
#include <cuda_runtime.h>

// D_KNN: soft-kNN imputation.
//   inputs (metadata order): X_train [N,64] f32, y_train [N,64] f32, X_missing [64] f32
//   output: [1,64] f32 = sum_{k in top32 by weight} softmax(-dist)_k * y_train[k]
//
// Pipeline: init (zero Z) -> pass1 (stream 256MB: distances, Z, per-block exact
// top-32 via cascading atomicMin) -> final (merge block tops, gather y, emit).

#define NB1  592          // 4 blocks per SM on 148 SMs
#define T1   256
#define KSEL 32
#define DIMS 64

__device__ float g_Z;
__device__ unsigned long long g_btop[NB1 * KSEL];

// Exact k-min maintenance: cascade the candidate through the K slots with
// atomicMin, carrying the displaced (larger) value forward. A value only
// drops off the end after K strictly-smaller values exist in the slots, so
// the final slot contents are exactly the K smallest keys ever inserted.
// The value dropped off the end is >= the current (and all future) slot max,
// so it is a safe monotone prefilter threshold.
__device__ __forceinline__ void cascade_insert(unsigned long long* slots,
                                               unsigned int* s_thresh,
                                               unsigned long long v) {
    bool full = true;
    #pragma unroll 1
    for (int j = 0; j < KSEL; j++) {
        unsigned long long old = atomicMin(&slots[j], v);
        if (old == 0xFFFFFFFFFFFFFFFFULL) { full = false; break; }  // filled an empty slot
        if (old > v) v = old;                                        // carry displaced max
    }
    if (full) atomicMin(s_thresh, (unsigned int)(v >> 32));
}

__global__ void knn_init() { g_Z = 0.0f; }

__global__ void __launch_bounds__(T1)
knn_pass1(const float* __restrict__ X, const float* __restrict__ q, int N) {
    __shared__ unsigned long long slots[KSEL];
    __shared__ unsigned int s_thresh;
    __shared__ float s_z;

    const int tid = threadIdx.x;
    if (tid < KSEL) slots[tid] = 0xFFFFFFFFFFFFFFFFULL;
    if (tid == 0) { s_thresh = 0xFFFFFFFFu; s_z = 0.0f; }
    __syncthreads();

    const int lane = tid & 31;
    const int sub  = lane & 7;   // column-slice owner (8 lanes per row)
    const int rsel = lane >> 3;  // which of the 4 rows this warp-iter
    const int gw   = blockIdx.x * (T1 / 32) + (tid >> 5);
    const int nw   = NB1 * (T1 / 32);

    // Each lane holds its 8-float slice of the query.
    const float4* qv = (const float4*)q;
    const float4 qa = __ldg(qv + sub * 2);
    const float4 qb = __ldg(qv + sub * 2 + 1);

    float wsum = 0.0f;
    for (int base = gw * 4; base < N; base += nw * 4) {
        const int r  = base + rsel;
        const int rc = min(r, N - 1);  // clamp so all lanes load (shfl needs full warp)
        const float4* xp = (const float4*)(X + (size_t)rc * DIMS) + sub * 2;
        const float4 xa = __ldg(xp);
        const float4 xb = __ldg(xp + 1);
        float t, ss = 0.0f;
        t = xa.x - qa.x; ss = fmaf(t, t, ss);
        t = xa.y - qa.y; ss = fmaf(t, t, ss);
        t = xa.z - qa.z; ss = fmaf(t, t, ss);
        t = xa.w - qa.w; ss = fmaf(t, t, ss);
        t = xb.x - qb.x; ss = fmaf(t, t, ss);
        t = xb.y - qb.y; ss = fmaf(t, t, ss);
        t = xb.z - qb.z; ss = fmaf(t, t, ss);
        t = xb.w - qb.w; ss = fmaf(t, t, ss);
        // reduce across the 8-lane group
        ss += __shfl_xor_sync(0xffffffffu, ss, 1);
        ss += __shfl_xor_sync(0xffffffffu, ss, 2);
        ss += __shfl_xor_sync(0xffffffffu, ss, 4);

        if (sub == 0 && r < N) {
            const float d = sqrtf(ss);
            wsum += expf(-d);  // softmax denominator term (TAU = 1)
            const unsigned int db = __float_as_uint(d);  // positive f32: bits monotone
            if (db <= *(volatile unsigned int*)&s_thresh) {
                cascade_insert(slots, &s_thresh,
                               ((unsigned long long)db << 32) | (unsigned int)r);
            }
        }
    }

    // block-reduce the denominator, one global atomic per block
    #pragma unroll
    for (int o = 16; o > 0; o >>= 1) wsum += __shfl_xor_sync(0xffffffffu, wsum, o);
    if (lane == 0) atomicAdd(&s_z, wsum);
    __syncthreads();
    if (tid == 0) atomicAdd(&g_Z, s_z);
    if (tid < KSEL) g_btop[blockIdx.x * KSEL + tid] = slots[tid];
}

__global__ void knn_final(const float* __restrict__ Y, float* __restrict__ out) {
    __shared__ unsigned long long slots[KSEL];
    __shared__ unsigned int s_thresh;
    __shared__ float wv[KSEL];
    __shared__ int   iv[KSEL];
    __shared__ float zinv;

    const int tid = threadIdx.x;
    if (tid < KSEL) slots[tid] = 0xFFFFFFFFFFFFFFFFULL;
    if (tid == 0) s_thresh = 0xFFFFFFFFu;
    __syncthreads();

    for (int i = tid; i < NB1 * KSEL; i += blockDim.x) {
        const unsigned long long v = g_btop[i];
        if ((unsigned int)(v >> 32) <= *(volatile unsigned int*)&s_thresh)
            cascade_insert(slots, &s_thresh, v);
    }
    __syncthreads();

    if (tid < KSEL) {
        const unsigned long long v = slots[tid];
        if (v == 0xFFFFFFFFFFFFFFFFULL) { wv[tid] = 0.0f; iv[tid] = 0; }
        else {
            wv[tid] = expf(-__uint_as_float((unsigned int)(v >> 32)));
            iv[tid] = (int)(v & 0xFFFFFFFFu);
        }
    }
    if (tid == 0) zinv = 1.0f / g_Z;
    __syncthreads();

    if (tid < DIMS) {
        float acc = 0.0f;
        #pragma unroll
        for (int k = 0; k < KSEL; k++)
            acc += wv[k] * __ldg(Y + (size_t)iv[k] * DIMS + tid);
        out[tid] = acc * zinv;
    }
}

extern "C" void kernel_launch(void* const* d_in, const int* in_sizes, int n_in,
                              void* d_out, int out_size) {
    const float* X = (const float*)d_in[0];  // X_train [N,64]
    const float* Y = (const float*)d_in[1];  // y_train [N,64]
    const float* q = (const float*)d_in[2];  // X_missing [64]
    float* out = (float*)d_out;              // [1,64] f32
    const int N = in_sizes[0] / DIMS;

    knn_init<<<1, 32>>>();
    knn_pass1<<<NB1, T1>>>(X, q, N);
    knn_final<<<1, 64>>>(Y, out);
}

// round 6
// speedup vs baseline: 6.4748x; 6.4748x over previous
#include <cuda_runtime.h>
#include <math_constants.h>

// D_KNN soft-kNN imputation, contention-free top-k.
//   inputs: X_train [N,64] f32, y_train [N,64] f32, X_missing [64] f32
//   output: [1,64] f32
//
// pass1: stream 256MB, per-warp register top-32 (ballot fast path, shfl insert),
//        bitonic merge to sorted per-block top-32 + per-block partial Z.
// final: merge 592 sorted lists (1-compare block skip), gather y, emit.

#define NB1  592         // 4 blocks/SM on 148 SMs
#define T1   256
#define KSEL 32
#define DIMS 64

typedef unsigned long long u64;
typedef unsigned int u32;

__device__ u64   g_btop[NB1 * KSEL];  // per-block sorted top-32 keys
__device__ float g_bz[NB1];           // per-block partial softmax denominator

// ---- warp-collective helpers (all 32 lanes participate) ----

// Replace current warp-max-held key with cand (guaranteed smaller); refresh mhi.
// Argmax reduce is lexicographic on (value, lane): ties (sentinels) converge to
// ONE lane warp-wide. (Strict-greater-only here was the R1 correctness bug: all
// lanes tied at ~0ull kept l==lane, so every lane replaced its key.)
__device__ __forceinline__ void winsert(u64& held, u32& mhi, u64 cand, int lane) {
    u64 v = held; int l = lane;
    #pragma unroll
    for (int off = 16; off; off >>= 1) {
        u64 ov = __shfl_xor_sync(0xffffffffu, v, off);
        int ol = __shfl_xor_sync(0xffffffffu, l, off);
        if (ov > v || (ov == v && ol > l)) { v = ov; l = ol; }
    }
    if (lane == l) held = cand;          // cand < v guaranteed by caller's filter
    u64 v2 = held;
    #pragma unroll
    for (int off = 16; off; off >>= 1) {
        u64 ov = __shfl_xor_sync(0xffffffffu, v2, off);
        if (ov > v2) v2 = ov;
    }
    mhi = (u32)(v2 >> 32);
}

// Full bitonic sort of one key per lane, ascending by lane.
__device__ __forceinline__ u64 bsort32(u64 key, int lane) {
    #pragma unroll
    for (int k = 2; k <= 32; k <<= 1) {
        #pragma unroll
        for (int j = k >> 1; j; j >>= 1) {
            u64 p = __shfl_xor_sync(0xffffffffu, key, j);
            bool up = ((lane & k) == 0);
            bool lower = ((lane & j) == 0);
            bool keepMin = (lower == up);
            key = keepMin ? (key < p ? key : p) : (key > p ? key : p);
        }
    }
    return key;
}

// Bitonic sequence -> ascending (5 steps).
__device__ __forceinline__ u64 bmerge32(u64 key, int lane) {
    #pragma unroll
    for (int j = 16; j; j >>= 1) {
        u64 p = __shfl_xor_sync(0xffffffffu, key, j);
        bool lower = ((lane & j) == 0);
        key = lower ? (key < p ? key : p) : (key > p ? key : p);
    }
    return key;
}

// ---- pass 1: stream X, distances, Z, per-block sorted top-32 ----

__global__ void __launch_bounds__(T1)
knn_pass1(const float* __restrict__ X, const float* __restrict__ q, int N) {
    __shared__ u64 s_lists[T1 / 32][KSEL];
    __shared__ float s_z[T1 / 32];

    const int tid  = threadIdx.x;
    const int lane = tid & 31;
    const int warp = tid >> 5;
    const int sub  = lane & 7;   // 8 lanes per row (32B each, coalesced)
    const int rsel = lane >> 3;  // which of 4 rows in a quad
    const int gw   = blockIdx.x * (T1 / 32) + warp;
    const int nw   = NB1 * (T1 / 32);

    const float4* qv = (const float4*)q;
    const float4 qa = __ldg(qv + sub * 2);
    const float4 qb = __ldg(qv + sub * 2 + 1);

    u64 held = ~0ull;
    u32 mhi  = 0xFFFFFFFFu;
    float wsum = 0.0f;

    for (int base = gw * 8; base < N; base += nw * 8) {
        const int r0 = base + rsel;
        const int r1 = base + 4 + rsel;
        const int rc0 = min(r0, N - 1);
        const int rc1 = min(r1, N - 1);
        const float4* p0 = (const float4*)(X + (size_t)rc0 * DIMS) + sub * 2;
        const float4* p1 = (const float4*)(X + (size_t)rc1 * DIMS) + sub * 2;
        const float4 a0 = __ldg(p0), b0 = __ldg(p0 + 1);
        const float4 a1 = __ldg(p1), b1 = __ldg(p1 + 1);

        float t, ss0 = 0.0f, ss1 = 0.0f;
        t = a0.x - qa.x; ss0 = fmaf(t, t, ss0);
        t = a0.y - qa.y; ss0 = fmaf(t, t, ss0);
        t = a0.z - qa.z; ss0 = fmaf(t, t, ss0);
        t = a0.w - qa.w; ss0 = fmaf(t, t, ss0);
        t = b0.x - qb.x; ss0 = fmaf(t, t, ss0);
        t = b0.y - qb.y; ss0 = fmaf(t, t, ss0);
        t = b0.z - qb.z; ss0 = fmaf(t, t, ss0);
        t = b0.w - qb.w; ss0 = fmaf(t, t, ss0);
        t = a1.x - qa.x; ss1 = fmaf(t, t, ss1);
        t = a1.y - qa.y; ss1 = fmaf(t, t, ss1);
        t = a1.z - qa.z; ss1 = fmaf(t, t, ss1);
        t = a1.w - qa.w; ss1 = fmaf(t, t, ss1);
        t = b1.x - qb.x; ss1 = fmaf(t, t, ss1);
        t = b1.y - qb.y; ss1 = fmaf(t, t, ss1);
        t = b1.z - qb.z; ss1 = fmaf(t, t, ss1);
        t = b1.w - qb.w; ss1 = fmaf(t, t, ss1);

        ss0 += __shfl_xor_sync(0xffffffffu, ss0, 1);
        ss1 += __shfl_xor_sync(0xffffffffu, ss1, 1);
        ss0 += __shfl_xor_sync(0xffffffffu, ss0, 2);
        ss1 += __shfl_xor_sync(0xffffffffu, ss1, 2);
        ss0 += __shfl_xor_sync(0xffffffffu, ss0, 4);
        ss1 += __shfl_xor_sync(0xffffffffu, ss1, 4);

        float d0 = sqrtf(ss0); if (r0 >= N) d0 = CUDART_INF_F;
        float d1 = sqrtf(ss1); if (r1 >= N) d1 = CUDART_INF_F;
        wsum += __expf(-d0) + __expf(-d1);   // every row counted 8x; /8 at the end

        const u32 db0 = __float_as_uint(d0);
        const u32 db1 = __float_as_uint(d1);
        const unsigned bal0 = __ballot_sync(0xffffffffu, db0 < mhi && r0 < N);
        const unsigned bal1 = __ballot_sync(0xffffffffu, db1 < mhi && r1 < N);

        if (bal0 | bal1) {  // warp-uniform, rare
            #pragma unroll
            for (int g = 0; g < 4; g++) {
                if (bal0 & (1u << (g * 8))) {
                    const u32 dv = __shfl_sync(0xffffffffu, db0, g * 8);
                    if (dv < mhi)
                        winsert(held, mhi, ((u64)dv << 32) | (u32)(base + g), lane);
                }
                if (bal1 & (1u << (g * 8))) {
                    const u32 dv = __shfl_sync(0xffffffffu, db1, g * 8);
                    if (dv < mhi)
                        winsert(held, mhi, ((u64)dv << 32) | (u32)(base + 4 + g), lane);
                }
            }
        }
    }

    // epilogue: sort, merge warps, write block results
    held = bsort32(held, lane);
    s_lists[warp][lane] = held;

    #pragma unroll
    for (int off = 16; off; off >>= 1) wsum += __shfl_xor_sync(0xffffffffu, wsum, off);
    if (lane == 0) s_z[warp] = wsum;
    __syncthreads();

    if (warp == 0) {
        u64 a = s_lists[0][lane];
        #pragma unroll
        for (int w = 1; w < T1 / 32; w++) {
            u64 b = s_lists[w][31 - lane];   // reversed read of sorted list
            a = (a < b) ? a : b;             // 32 smallest of union (bitonic)
            a = bmerge32(a, lane);
        }
        g_btop[blockIdx.x * KSEL + lane] = a;
    }
    if (tid == 0) {
        float z = 0.0f;
        #pragma unroll
        for (int w = 0; w < T1 / 32; w++) z += s_z[w];
        g_bz[blockIdx.x] = z * 0.125f;
    }
}

// ---- final: merge 592 sorted lists, gather y rows, emit ----

__global__ void __launch_bounds__(256)
knn_final(const float* __restrict__ Y, float* __restrict__ out) {
    __shared__ u64 s_lists[8][KSEL];
    __shared__ float s_part[256];
    __shared__ float wv[KSEL];
    __shared__ int   iv[KSEL];
    __shared__ float zinv_s;

    const int tid = threadIdx.x;
    const int lane = tid & 31;
    const int warp = tid >> 5;

    // each warp merges 74 sorted block-lists; sorted => 1-compare skip
    u64 held = ~0ull;
    u64 hmax = ~0ull;
    for (int b = warp; b < NB1; b += 8) {
        const u64 e = g_btop[b * KSEL + lane];          // coalesced 256B
        const u64 bmin = __shfl_sync(0xffffffffu, e, 0);
        if (bmin < hmax) {
            const u64 br = __shfl_sync(0xffffffffu, e, 31 - lane);
            held = (held < br) ? held : br;
            held = bmerge32(held, lane);
            hmax = __shfl_sync(0xffffffffu, held, 31);
        }
    }
    s_lists[warp][lane] = held;

    // partial Z sums
    float z = 0.0f;
    for (int i = tid; i < NB1; i += 256) z += g_bz[i];
    s_part[tid] = z;
    __syncthreads();

    if (warp == 0) {
        u64 a = s_lists[0][lane];
        #pragma unroll
        for (int w = 1; w < 8; w++) {
            u64 b = s_lists[w][31 - lane];
            a = (a < b) ? a : b;
            a = bmerge32(a, lane);
        }
        if (a == ~0ull) { wv[lane] = 0.0f; iv[lane] = 0; }
        else {
            wv[lane] = __expf(-__uint_as_float((u32)(a >> 32)));
            iv[lane] = (int)(u32)a;
        }
    }
    __syncthreads();
    if (tid == 0) {
        float t = 0.0f;
        for (int i = 0; i < 256; i++) t += s_part[i];
        zinv_s = 1.0f / t;
    }
    __syncthreads();

    if (tid < DIMS) {
        float acc = 0.0f;
        #pragma unroll
        for (int k = 0; k < KSEL; k++)
            acc += wv[k] * __ldg(Y + (size_t)iv[k] * DIMS + tid);
        out[tid] = acc * zinv_s;
    }
}

extern "C" void kernel_launch(void* const* d_in, const int* in_sizes, int n_in,
                              void* d_out, int out_size) {
    const float* X = (const float*)d_in[0];
    const float* Y = (const float*)d_in[1];
    const float* q = (const float*)d_in[2];
    float* out = (float*)d_out;
    const int N = in_sizes[0] / DIMS;

    knn_pass1<<<NB1, T1>>>(X, q, N);
    knn_final<<<1, 256>>>(Y, out);
}

// round 7
// speedup vs baseline: 7.4660x; 1.1531x over previous
#include <cuda_runtime.h>
#include <math_constants.h>

// D_KNN soft-kNN imputation, contention-free top-k.
//   inputs: X_train [N,64] f32, y_train [N,64] f32, X_missing [64] f32
//   output: [1,64] f32
//
// pass1 (444 blocks x 256): stream 256MB @ 16 rows/warp-iter (8 LDG.128/thread
//   in flight), per-warp register top-32 (ballot prefilter + shfl insert),
//   bitonic epilogue -> sorted per-block top-32 + partial Z.
// final (1 block x 1024): 32 warps merge 444 sorted lists with prefetch +
//   1-compare skip, 5-level tree merge, gather y, emit.

#define NB1  444         // 3 blocks/SM on 148 SMs (one balanced wave @ ~80 regs)
#define T1   256
#define KSEL 32
#define DIMS 64

typedef unsigned long long u64;
typedef unsigned int u32;

__device__ u64   g_btop[NB1 * KSEL];  // per-block sorted top-32 keys
__device__ float g_bz[NB1];           // per-block partial softmax denominator

// ---- warp-collective helpers (all 32 lanes participate) ----

// Replace current warp-max-held key with cand (caller guarantees cand < max).
// Lexicographic (value, lane) argmax so sentinel ties converge to ONE lane.
__device__ __forceinline__ void winsert(u64& held, u32& mhi, u64 cand, int lane) {
    u64 v = held; int l = lane;
    #pragma unroll
    for (int off = 16; off; off >>= 1) {
        u64 ov = __shfl_xor_sync(0xffffffffu, v, off);
        int ol = __shfl_xor_sync(0xffffffffu, l, off);
        if (ov > v || (ov == v && ol > l)) { v = ov; l = ol; }
    }
    if (lane == l) held = cand;
    u64 v2 = held;
    #pragma unroll
    for (int off = 16; off; off >>= 1) {
        u64 ov = __shfl_xor_sync(0xffffffffu, v2, off);
        if (ov > v2) v2 = ov;
    }
    mhi = (u32)(v2 >> 32);
}

// Full bitonic sort of one key per lane, ascending by lane.
__device__ __forceinline__ u64 bsort32(u64 key, int lane) {
    #pragma unroll
    for (int k = 2; k <= 32; k <<= 1) {
        #pragma unroll
        for (int j = k >> 1; j; j >>= 1) {
            u64 p = __shfl_xor_sync(0xffffffffu, key, j);
            bool up = ((lane & k) == 0);
            bool lower = ((lane & j) == 0);
            bool keepMin = (lower == up);
            key = keepMin ? (key < p ? key : p) : (key > p ? key : p);
        }
    }
    return key;
}

// Bitonic sequence -> ascending (5 steps).
__device__ __forceinline__ u64 bmerge32(u64 key, int lane) {
    #pragma unroll
    for (int j = 16; j; j >>= 1) {
        u64 p = __shfl_xor_sync(0xffffffffu, key, j);
        bool lower = ((lane & j) == 0);
        key = lower ? (key < p ? key : p) : (key > p ? key : p);
    }
    return key;
}

// Merge two sorted ascending 32-lists (one key/lane) -> sorted 32 smallest.
__device__ __forceinline__ u64 merge_sorted(u64 a, u64 b, int lane) {
    u64 br = __shfl_sync(0xffffffffu, b, 31 - lane);
    a = (a < br) ? a : br;
    return bmerge32(a, lane);
}

// squared-distance slice for one row (8 floats per lane)
__device__ __forceinline__ float dist8(float4 a, float4 b, float4 qa, float4 qb) {
    float t, ss = 0.0f;
    t = a.x - qa.x; ss = fmaf(t, t, ss);
    t = a.y - qa.y; ss = fmaf(t, t, ss);
    t = a.z - qa.z; ss = fmaf(t, t, ss);
    t = a.w - qa.w; ss = fmaf(t, t, ss);
    t = b.x - qb.x; ss = fmaf(t, t, ss);
    t = b.y - qb.y; ss = fmaf(t, t, ss);
    t = b.z - qb.z; ss = fmaf(t, t, ss);
    t = b.w - qb.w; ss = fmaf(t, t, ss);
    return ss;
}

// ---- pass 1: stream X, distances, Z, per-block sorted top-32 ----

__global__ void __launch_bounds__(T1)
knn_pass1(const float* __restrict__ X, const float* __restrict__ q, int N) {
    __shared__ u64 s_lists[T1 / 32][KSEL];
    __shared__ float s_z[T1 / 32];

    const int tid  = threadIdx.x;
    const int lane = tid & 31;
    const int warp = tid >> 5;
    const int sub  = lane & 7;   // 8 lanes per row (32B each, coalesced)
    const int rsel = lane >> 3;  // which of 4 rows in a quad
    const int gw   = blockIdx.x * (T1 / 32) + warp;
    const int nw   = NB1 * (T1 / 32);

    const float4* qv = (const float4*)q;
    const float4 qa = __ldg(qv + sub * 2);
    const float4 qb = __ldg(qv + sub * 2 + 1);

    u64 held = ~0ull;
    u32 mhi  = 0xFFFFFFFFu;
    float wsum = 0.0f;

    for (int base = gw * 16; base < N; base += nw * 16) {
        int   r[4];
        float ss[4];
        float4 xa[4], xb[4];
        #pragma unroll
        for (int i = 0; i < 4; i++) {
            r[i] = base + i * 4 + rsel;
            const int rc = min(r[i], N - 1);
            const float4* p = (const float4*)(X + (size_t)rc * DIMS) + sub * 2;
            xa[i] = __ldg(p);
            xb[i] = __ldg(p + 1);
        }
        #pragma unroll
        for (int i = 0; i < 4; i++) ss[i] = dist8(xa[i], xb[i], qa, qb);

        #pragma unroll
        for (int i = 0; i < 4; i++) {
            ss[i] += __shfl_xor_sync(0xffffffffu, ss[i], 1);
            ss[i] += __shfl_xor_sync(0xffffffffu, ss[i], 2);
            ss[i] += __shfl_xor_sync(0xffffffffu, ss[i], 4);
        }

        float d[4];
        u32 db[4];
        unsigned bal[4];
        unsigned any = 0;
        #pragma unroll
        for (int i = 0; i < 4; i++) {
            d[i] = sqrtf(ss[i]);
            if (r[i] >= N) d[i] = CUDART_INF_F;
            wsum += __expf(-d[i]);          // counted 8x/row; /8 at the end
            db[i] = __float_as_uint(d[i]);
            bal[i] = __ballot_sync(0xffffffffu, db[i] < mhi && r[i] < N);
            any |= bal[i];
        }

        if (any) {  // warp-uniform, rare
            #pragma unroll
            for (int i = 0; i < 4; i++) {
                if (!bal[i]) continue;
                #pragma unroll
                for (int g = 0; g < 4; g++) {
                    if (bal[i] & (1u << (g * 8))) {
                        const u32 dv = __shfl_sync(0xffffffffu, db[i], g * 8);
                        if (dv < mhi)
                            winsert(held, mhi,
                                    ((u64)dv << 32) | (u32)(base + i * 4 + g), lane);
                    }
                }
            }
        }
    }

    // epilogue: sort, merge warps, write block results
    held = bsort32(held, lane);
    s_lists[warp][lane] = held;

    #pragma unroll
    for (int off = 16; off; off >>= 1) wsum += __shfl_xor_sync(0xffffffffu, wsum, off);
    if (lane == 0) s_z[warp] = wsum;
    __syncthreads();

    if (warp == 0) {
        u64 a = s_lists[0][lane];
        #pragma unroll
        for (int w = 1; w < T1 / 32; w++) a = merge_sorted(a, s_lists[w][lane], lane);
        g_btop[blockIdx.x * KSEL + lane] = a;
    }
    if (tid == 0) {
        float z = 0.0f;
        #pragma unroll
        for (int w = 0; w < T1 / 32; w++) z += s_z[w];
        g_bz[blockIdx.x] = z * 0.125f;
    }
}

// ---- final: merge 444 sorted lists, gather y rows, emit ----

__global__ void __launch_bounds__(1024)
knn_final(const float* __restrict__ Y, float* __restrict__ out) {
    __shared__ u64 s_lists[32][KSEL];
    __shared__ float s_zw[32];
    __shared__ float wv[KSEL];
    __shared__ int   iv[KSEL];
    __shared__ float zinv_s;

    const int tid  = threadIdx.x;
    const int lane = tid & 31;
    const int warp = tid >> 5;

    // each warp merges ~14 sorted lists; prefetch next, 1-compare skip
    u64 held = g_btop[warp * KSEL + lane];   // already sorted ascending
    u64 hmax = __shfl_sync(0xffffffffu, held, 31);
    u64 e = (warp + 32 < NB1) ? g_btop[(warp + 32) * KSEL + lane] : ~0ull;
    for (int b = warp + 32; b < NB1; b += 32) {
        const int bn = b + 32;
        const u64 e_next = (bn < NB1) ? g_btop[bn * KSEL + lane] : ~0ull;
        const u64 bmin = __shfl_sync(0xffffffffu, e, 0);
        if (bmin < hmax) {
            held = merge_sorted(held, e, lane);
            hmax = __shfl_sync(0xffffffffu, held, 31);
        }
        e = e_next;
    }
    s_lists[warp][lane] = held;

    // partial Z
    float z = 0.0f;
    for (int i = tid; i < NB1; i += 1024) z += g_bz[i];
    #pragma unroll
    for (int off = 16; off; off >>= 1) z += __shfl_xor_sync(0xffffffffu, z, off);
    if (lane == 0) s_zw[warp] = z;

    // tree-merge 32 sorted lists in 5 levels (parallel warps)
    #pragma unroll
    for (int nl = 16; nl >= 1; nl >>= 1) {
        __syncthreads();
        if (warp < nl) {
            u64 a = s_lists[2 * warp][lane];
            u64 b = s_lists[2 * warp + 1][lane];
            s_lists[warp][lane] = merge_sorted(a, b, lane);
        }
    }
    __syncthreads();

    if (warp == 0) {
        const u64 a = s_lists[0][lane];
        if (a == ~0ull) { wv[lane] = 0.0f; iv[lane] = 0; }
        else {
            wv[lane] = __expf(-__uint_as_float((u32)(a >> 32)));
            iv[lane] = (int)(u32)a;
        }
    }
    if (tid == 0) {
        float t = 0.0f;
        #pragma unroll
        for (int w = 0; w < 32; w++) t += s_zw[w];
        zinv_s = 1.0f / t;
    }
    __syncthreads();

    if (tid < DIMS) {
        float acc = 0.0f;
        #pragma unroll
        for (int k = 0; k < KSEL; k++)
            acc += wv[k] * __ldg(Y + (size_t)iv[k] * DIMS + tid);
        out[tid] = acc * zinv_s;
    }
}

extern "C" void kernel_launch(void* const* d_in, const int* in_sizes, int n_in,
                              void* d_out, int out_size) {
    const float* X = (const float*)d_in[0];
    const float* Y = (const float*)d_in[1];
    const float* q = (const float*)d_in[2];
    float* out = (float*)d_out;
    const int N = in_sizes[0] / DIMS;

    knn_pass1<<<NB1, T1>>>(X, q, N);
    knn_final<<<1, 1024>>>(Y, out);
}